// round 15
// baseline (speedup 1.0000x reference)
#include <cuda_runtime.h>
#include <math.h>

#define G    4384
#define D    128
#define B    8
#define H1   64
#define NOUT 26
#define NQC  16
#define QCH  (G / NQC)        // 274

// ---------------- device scratch ----------------
__device__ float4 g_P4[G];    // P'[k] = (W_in @ K^T)*scale*log2e
__device__ float  g_c[G];     // c'[k]
__device__ float  g_R[B * G]; // 1/Z per (b,q)
__device__ float  g_w[B * G]; // softmax column sums (atomic accumulation)
__device__ float  g_mean[B * D]; // mean partials (atomic accumulation)

__device__ __forceinline__ float ex2f(float x) {
    float e; asm("ex2.approx.f32 %0, %1;" : "=f"(e) : "f"(x)); return e;
}
__device__ __forceinline__ unsigned long long pk2(float lo, float hi) {
    unsigned long long d;
    asm("mov.b64 %0, {%1,%2};" : "=l"(d) : "f"(lo), "f"(hi));
    return d;
}
__device__ __forceinline__ unsigned long long fma2(unsigned long long a,
                                                   unsigned long long b,
                                                   unsigned long long c) {
    unsigned long long d;
    asm("fma.rn.f32x2 %0, %1, %2, %3;" : "=l"(d) : "l"(a), "l"(b), "l"(c));
    return d;
}
__device__ __forceinline__ void unpk2(unsigned long long v, float& lo, float& hi) {
    asm("mov.b64 {%0,%1}, %2;" : "=f"(lo), "=f"(hi) : "l"(v));
}

// ---------------- K0: P[4,G], c[G], zero g_w + g_mean ----------------
__global__ void k0_P(const float* __restrict__ Win, const float* __restrict__ bin,
                     const float* __restrict__ Kp) {
    int gtid = blockIdx.x * blockDim.x + threadIdx.x;
    if (gtid < B * G) g_w[gtid] = 0.f;
    if (gtid < B * D) g_mean[gtid] = 0.f;

    int warp = gtid >> 5;
    int lane = threadIdx.x & 31;
    if (warp >= G) return;
    const float S = 1.4426950408889634f * 0.08838834764831843f;  // log2e / sqrt(128)
    float a0 = 0.f, a1 = 0.f, a2 = 0.f, a3 = 0.f, cb = 0.f;
    const float* krow = Kp + (size_t)warp * D;
#pragma unroll
    for (int i = 0; i < 4; i++) {
        int d = lane + 32 * i;
        float kv = krow[d];
        a0 = fmaf(kv, Win[0 * D + d], a0);
        a1 = fmaf(kv, Win[1 * D + d], a1);
        a2 = fmaf(kv, Win[2 * D + d], a2);
        a3 = fmaf(kv, Win[3 * D + d], a3);
        cb = fmaf(kv, bin[d], cb);
    }
#pragma unroll
    for (int off = 16; off; off >>= 1) {
        a0 += __shfl_down_sync(0xffffffffu, a0, off);
        a1 += __shfl_down_sync(0xffffffffu, a1, off);
        a2 += __shfl_down_sync(0xffffffffu, a2, off);
        a3 += __shfl_down_sync(0xffffffffu, a3, off);
        cb += __shfl_down_sync(0xffffffffu, cb, off);
    }
    if (lane == 0) {
        g_P4[warp] = make_float4(a0 * S, a1 * S, a2 * S, a3 * S);
        g_c[warp]  = cb * S;
    }
}

// ---------------- K1: row sums Z -> 1/Z (fp32 ex2; R12-validated) ----------------
__global__ void __launch_bounds__(256) k1_Z(const float* __restrict__ mut) {
    const int tid  = threadIdx.x;
    const int lane = tid & 31, warp = tid >> 5;
    const int b    = blockIdx.y;
    const int q0   = blockIdx.x * 32 + warp * 4;

    float4 m0 = __ldg((const float4*)mut + (size_t)b * G + q0);
    float4 m1 = __ldg((const float4*)mut + (size_t)b * G + q0 + 1);
    float4 m2 = __ldg((const float4*)mut + (size_t)b * G + q0 + 2);
    float4 m3 = __ldg((const float4*)mut + (size_t)b * G + q0 + 3);
    unsigned long long pmx01 = pk2(m0.x, m1.x), pmy01 = pk2(m0.y, m1.y);
    unsigned long long pmz01 = pk2(m0.z, m1.z), pmw01 = pk2(m0.w, m1.w);
    unsigned long long pmx23 = pk2(m2.x, m3.x), pmy23 = pk2(m2.y, m3.y);
    unsigned long long pmz23 = pk2(m2.z, m3.z), pmw23 = pk2(m2.w, m3.w);

    float z0 = 0.f, z1 = 0.f, z2 = 0.f, z3 = 0.f;
    for (int k = lane; k < G; k += 32) {
        float4 p = __ldg(&g_P4[k]);
        float  c = __ldg(&g_c[k]);
        unsigned long long px = pk2(p.x, p.x), py = pk2(p.y, p.y);
        unsigned long long pz = pk2(p.z, p.z), pw = pk2(p.w, p.w);
        unsigned long long cc = pk2(c, c);

        unsigned long long s01 = fma2(pmw01, pw, cc);
        s01 = fma2(pmz01, pz, s01);
        s01 = fma2(pmy01, py, s01);
        s01 = fma2(pmx01, px, s01);
        unsigned long long s23 = fma2(pmw23, pw, cc);
        s23 = fma2(pmz23, pz, s23);
        s23 = fma2(pmy23, py, s23);
        s23 = fma2(pmx23, px, s23);

        float sa, sb, sc2, sd;
        unpk2(s01, sa, sb);
        unpk2(s23, sc2, sd);
        z0 += ex2f(sa);
        z1 += ex2f(sb);
        z2 += ex2f(sc2);
        z3 += ex2f(sd);
    }
#pragma unroll
    for (int off = 16; off; off >>= 1) {
        z0 += __shfl_down_sync(0xffffffffu, z0, off);
        z1 += __shfl_down_sync(0xffffffffu, z1, off);
        z2 += __shfl_down_sync(0xffffffffu, z2, off);
        z3 += __shfl_down_sync(0xffffffffu, z3, off);
    }
    if (lane == 0) {
        float* rp = g_R + (size_t)b * G + q0;
        rp[0] = 1.0f / z0;
        rp[1] = 1.0f / z1;
        rp[2] = 1.0f / z2;
        rp[3] = 1.0f / z3;
    }
}

// ---------------- K2: column sums w[b,k] (fp32 ex2; R12-validated) ----------------
__global__ void __launch_bounds__(256) k2_W(const float* __restrict__ mut) {
    __shared__ float4 sm[QCH];
    __shared__ float  srr[QCH];
    const int tid = threadIdx.x;
    const int b   = blockIdx.z;
    const int qs  = blockIdx.y * QCH;

    for (int i = tid; i < QCH; i += 256) {
        sm[i]  = __ldg((const float4*)mut + (size_t)b * G + qs + i);
        srr[i] = __ldg(&g_R[(size_t)b * G + qs + i]);
    }
    __syncthreads();

    const int kb = (blockIdx.x * 256 + tid) * 4;
    const bool valid = (kb < G);
    const int kc = valid ? kb : 0;

    float4 p0 = __ldg(&g_P4[kc + 0]), p1 = __ldg(&g_P4[kc + 1]);
    float4 p2 = __ldg(&g_P4[kc + 2]), p3 = __ldg(&g_P4[kc + 3]);
    float  c0 = __ldg(&g_c[kc + 0]),  c1 = __ldg(&g_c[kc + 1]);
    float  c2 = __ldg(&g_c[kc + 2]),  c3 = __ldg(&g_c[kc + 3]);
    unsigned long long pAx = pk2(p0.x, p1.x), pAy = pk2(p0.y, p1.y);
    unsigned long long pAz = pk2(p0.z, p1.z), pAw = pk2(p0.w, p1.w);
    unsigned long long cA  = pk2(c0, c1);
    unsigned long long pBx = pk2(p2.x, p3.x), pBy = pk2(p2.y, p3.y);
    unsigned long long pBz = pk2(p2.z, p3.z), pBw = pk2(p2.w, p3.w);
    unsigned long long cB  = pk2(c2, c3);

    unsigned long long wA = pk2(0.f, 0.f), wB = pk2(0.f, 0.f);
    for (int q = 0; q < QCH; q++) {
        float4 m = sm[q];
        float  r = srr[q];
        unsigned long long mx = pk2(m.x, m.x), my = pk2(m.y, m.y);
        unsigned long long mz = pk2(m.z, m.z), mw = pk2(m.w, m.w);
        unsigned long long rr = pk2(r, r);

        unsigned long long sA = fma2(mw, pAw, cA);
        sA = fma2(mz, pAz, sA);
        sA = fma2(my, pAy, sA);
        sA = fma2(mx, pAx, sA);
        unsigned long long sB = fma2(mw, pBw, cB);
        sB = fma2(mz, pBz, sB);
        sB = fma2(my, pBy, sB);
        sB = fma2(mx, pBx, sB);

        float s0, s1, s2, s3;
        unpk2(sA, s0, s1);
        unpk2(sB, s2, s3);
        unsigned long long eA = pk2(ex2f(s0), ex2f(s1));
        unsigned long long eB = pk2(ex2f(s2), ex2f(s3));
        wA = fma2(eA, rr, wA);
        wB = fma2(eB, rr, wB);
    }

    if (valid) {
        float w0, w1, w2, w3;
        unpk2(wA, w0, w1);
        unpk2(wB, w2, w3);
        float* dst = g_w + (size_t)b * G + kb;
        atomicAdd(dst + 0, w0);
        atomicAdd(dst + 1, w1);
        atomicAdd(dst + 2, w2);
        atomicAdd(dst + 3, w3);
    }
}

// ---------------- K3a: mean partials = w @ V (1096 blocks, 4 k/thread) ----------------
__global__ void __launch_bounds__(D) k3a(const float* __restrict__ V) {
    const int k0 = blockIdx.x * 4;   // 0..1095, 4 k each
    const int d  = threadIdx.x;      // 128

    float v0 = __ldg(&V[(size_t)(k0 + 0) * D + d]);
    float v1 = __ldg(&V[(size_t)(k0 + 1) * D + d]);
    float v2 = __ldg(&V[(size_t)(k0 + 2) * D + d]);
    float v3 = __ldg(&V[(size_t)(k0 + 3) * D + d]);

    float acc[B];
#pragma unroll
    for (int b = 0; b < B; b++) {
        const float* wr = g_w + b * G + k0;
        float a = wr[0] * v0;
        a = fmaf(wr[1], v1, a);
        a = fmaf(wr[2], v2, a);
        a = fmaf(wr[3], v3, a);
        acc[b] = a;
    }
#pragma unroll
    for (int b = 0; b < B; b++) atomicAdd(&g_mean[b * D + d], acc[b]);
}

// ---------------- K3b: GELU MLP head, ONE block, all batches (R12-validated) ----------------
__global__ void __launch_bounds__(512) k3b(const float* __restrict__ W1,
                                           const float* __restrict__ b1,
                                           const float* __restrict__ W2,
                                           const float* __restrict__ b2,
                                           float* __restrict__ out) {
    __shared__ float sW1[D * H1];       // 32 KB
    __shared__ float sW2[H1 * NOUT];    // 6656 B
    __shared__ float mean[B * D];       // 4 KB
    __shared__ float h[B * H1];         // 2 KB
    const int tid = threadIdx.x;        // 512

    for (int i = tid; i < D * H1 / 4; i += 512)
        ((float4*)sW1)[i] = __ldg((const float4*)W1 + i);
    for (int i = tid; i < H1 * NOUT; i += 512)
        sW2[i] = __ldg(&W2[i]);
    for (int i = tid; i < B * D; i += 512)
        mean[i] = g_mean[i] * (1.0f / (float)G);
    __syncthreads();

    {   // h: 512 outputs (b,hh), one per thread
        const int b = tid >> 6, hh = tid & 63;
        float a = b1[hh];
        const float* mrow = mean + b * D;
#pragma unroll 8
        for (int d = 0; d < D; d++)
            a = fmaf(mrow[d], sW1[d * H1 + hh], a);
        h[tid] = 0.5f * a * (1.0f + erff(a * 0.70710678118654752f));
    }
    __syncthreads();
    if (tid < B * NOUT) {   // 208 outputs (b,o)
        const int b = tid / NOUT, o = tid - b * NOUT;
        float s = b2[o];
        const float* hrow = h + b * H1;
#pragma unroll 8
        for (int j = 0; j < H1; j++)
            s = fmaf(hrow[j], sW2[j * NOUT + o], s);
        out[b * NOUT + o] = s;
    }
}

// ---------------- launch ----------------
extern "C" void kernel_launch(void* const* d_in, const int* in_sizes, int n_in,
                              void* d_out, int out_size) {
    const float* mut = (const float*)d_in[0];   // [8,4384,4]
    const float* V   = (const float*)d_in[1];   // [4384,128]
    const float* Win = (const float*)d_in[2];   // [4,128]
    const float* bin = (const float*)d_in[3];   // [128]
    const float* Kp  = (const float*)d_in[4];   // [4384,128]
    const float* W1  = (const float*)d_in[5];   // [128,64]
    const float* b1  = (const float*)d_in[6];   // [64]
    const float* W2  = (const float*)d_in[7];   // [64,26]
    const float* b2  = (const float*)d_in[8];   // [26]
    float* out = (float*)d_out;                 // [8,26]
    (void)in_sizes; (void)n_in; (void)out_size;

    k0_P<<<548, 256>>>(Win, bin, Kp);           // 4384 warps = G, + scratch zeroing
    k1_Z<<<dim3(G / 32, B), 256>>>(mut);        // (137, 8)
    k2_W<<<dim3(5, NQC, B), 256>>>(mut);        // 640 blocks
    k3a<<<1096, D>>>(V);                        // 4 k per thread, MLP=4
    k3b<<<1, 512>>>(W1, b1, W2, b2, out);
}

// round 16
// speedup vs baseline: 1.0454x; 1.0454x over previous
#include <cuda_runtime.h>
#include <math.h>

#define G    4384
#define D    128
#define B    8
#define H1   64
#define NOUT 26
#define NQC  16
#define QCH  (G / NQC)        // 274

// ---------------- device scratch ----------------
__device__ float4 g_P4[G];    // P'[k] = (W_in @ K^T)*scale*log2e
__device__ float  g_c[G];     // c'[k]
__device__ float  g_R[B * G]; // 1/Z per (b,q)
__device__ float  g_w[B * G]; // softmax column sums (atomic accumulation)
__device__ float  g_mean[B * D]; // mean partials (atomic accumulation)

__device__ __forceinline__ float ex2f(float x) {
    float e; asm("ex2.approx.f32 %0, %1;" : "=f"(e) : "f"(x)); return e;
}
__device__ __forceinline__ unsigned long long pk2(float lo, float hi) {
    unsigned long long d;
    asm("mov.b64 %0, {%1,%2};" : "=l"(d) : "f"(lo), "f"(hi));
    return d;
}
__device__ __forceinline__ unsigned long long fma2(unsigned long long a,
                                                   unsigned long long b,
                                                   unsigned long long c) {
    unsigned long long d;
    asm("fma.rn.f32x2 %0, %1, %2, %3;" : "=l"(d) : "l"(a), "l"(b), "l"(c));
    return d;
}
__device__ __forceinline__ void unpk2(unsigned long long v, float& lo, float& hi) {
    asm("mov.b64 {%0,%1}, %2;" : "=f"(lo), "=f"(hi) : "l"(v));
}

// ---------------- K0: P[4,G], c[G], zero g_w + g_mean ----------------
__global__ void k0_P(const float* __restrict__ Win, const float* __restrict__ bin,
                     const float* __restrict__ Kp) {
    int gtid = blockIdx.x * blockDim.x + threadIdx.x;
    if (gtid < B * G) g_w[gtid] = 0.f;
    if (gtid < B * D) g_mean[gtid] = 0.f;

    int warp = gtid >> 5;
    int lane = threadIdx.x & 31;
    if (warp >= G) return;
    const float S = 1.4426950408889634f * 0.08838834764831843f;  // log2e / sqrt(128)
    float a0 = 0.f, a1 = 0.f, a2 = 0.f, a3 = 0.f, cb = 0.f;
    const float* krow = Kp + (size_t)warp * D;
#pragma unroll
    for (int i = 0; i < 4; i++) {
        int d = lane + 32 * i;
        float kv = krow[d];
        a0 = fmaf(kv, Win[0 * D + d], a0);
        a1 = fmaf(kv, Win[1 * D + d], a1);
        a2 = fmaf(kv, Win[2 * D + d], a2);
        a3 = fmaf(kv, Win[3 * D + d], a3);
        cb = fmaf(kv, bin[d], cb);
    }
#pragma unroll
    for (int off = 16; off; off >>= 1) {
        a0 += __shfl_down_sync(0xffffffffu, a0, off);
        a1 += __shfl_down_sync(0xffffffffu, a1, off);
        a2 += __shfl_down_sync(0xffffffffu, a2, off);
        a3 += __shfl_down_sync(0xffffffffu, a3, off);
        cb += __shfl_down_sync(0xffffffffu, cb, off);
    }
    if (lane == 0) {
        g_P4[warp] = make_float4(a0 * S, a1 * S, a2 * S, a3 * S);
        g_c[warp]  = cb * S;
    }
}

// ---------------- K1: row sums Z -> 1/Z (fp32 ex2; validated) ----------------
__global__ void __launch_bounds__(256) k1_Z(const float* __restrict__ mut) {
    const int tid  = threadIdx.x;
    const int lane = tid & 31, warp = tid >> 5;
    const int b    = blockIdx.y;
    const int q0   = blockIdx.x * 32 + warp * 4;

    float4 m0 = __ldg((const float4*)mut + (size_t)b * G + q0);
    float4 m1 = __ldg((const float4*)mut + (size_t)b * G + q0 + 1);
    float4 m2 = __ldg((const float4*)mut + (size_t)b * G + q0 + 2);
    float4 m3 = __ldg((const float4*)mut + (size_t)b * G + q0 + 3);
    unsigned long long pmx01 = pk2(m0.x, m1.x), pmy01 = pk2(m0.y, m1.y);
    unsigned long long pmz01 = pk2(m0.z, m1.z), pmw01 = pk2(m0.w, m1.w);
    unsigned long long pmx23 = pk2(m2.x, m3.x), pmy23 = pk2(m2.y, m3.y);
    unsigned long long pmz23 = pk2(m2.z, m3.z), pmw23 = pk2(m2.w, m3.w);

    float z0 = 0.f, z1 = 0.f, z2 = 0.f, z3 = 0.f;
    for (int k = lane; k < G; k += 32) {
        float4 p = __ldg(&g_P4[k]);
        float  c = __ldg(&g_c[k]);
        unsigned long long px = pk2(p.x, p.x), py = pk2(p.y, p.y);
        unsigned long long pz = pk2(p.z, p.z), pw = pk2(p.w, p.w);
        unsigned long long cc = pk2(c, c);

        unsigned long long s01 = fma2(pmw01, pw, cc);
        s01 = fma2(pmz01, pz, s01);
        s01 = fma2(pmy01, py, s01);
        s01 = fma2(pmx01, px, s01);
        unsigned long long s23 = fma2(pmw23, pw, cc);
        s23 = fma2(pmz23, pz, s23);
        s23 = fma2(pmy23, py, s23);
        s23 = fma2(pmx23, px, s23);

        float sa, sb, sc2, sd;
        unpk2(s01, sa, sb);
        unpk2(s23, sc2, sd);
        z0 += ex2f(sa);
        z1 += ex2f(sb);
        z2 += ex2f(sc2);
        z3 += ex2f(sd);
    }
#pragma unroll
    for (int off = 16; off; off >>= 1) {
        z0 += __shfl_down_sync(0xffffffffu, z0, off);
        z1 += __shfl_down_sync(0xffffffffu, z1, off);
        z2 += __shfl_down_sync(0xffffffffu, z2, off);
        z3 += __shfl_down_sync(0xffffffffu, z3, off);
    }
    if (lane == 0) {
        float* rp = g_R + (size_t)b * G + q0;
        rp[0] = 1.0f / z0;
        rp[1] = 1.0f / z1;
        rp[2] = 1.0f / z2;
        rp[3] = 1.0f / z3;
    }
}

// ---------------- K2: column sums w[b,k] (fp32 ex2; validated) ----------------
__global__ void __launch_bounds__(256) k2_W(const float* __restrict__ mut) {
    __shared__ float4 sm[QCH];
    __shared__ float  srr[QCH];
    const int tid = threadIdx.x;
    const int b   = blockIdx.z;
    const int qs  = blockIdx.y * QCH;

    for (int i = tid; i < QCH; i += 256) {
        sm[i]  = __ldg((const float4*)mut + (size_t)b * G + qs + i);
        srr[i] = __ldg(&g_R[(size_t)b * G + qs + i]);
    }
    __syncthreads();

    const int kb = (blockIdx.x * 256 + tid) * 4;
    const bool valid = (kb < G);
    const int kc = valid ? kb : 0;

    float4 p0 = __ldg(&g_P4[kc + 0]), p1 = __ldg(&g_P4[kc + 1]);
    float4 p2 = __ldg(&g_P4[kc + 2]), p3 = __ldg(&g_P4[kc + 3]);
    float  c0 = __ldg(&g_c[kc + 0]),  c1 = __ldg(&g_c[kc + 1]);
    float  c2 = __ldg(&g_c[kc + 2]),  c3 = __ldg(&g_c[kc + 3]);
    unsigned long long pAx = pk2(p0.x, p1.x), pAy = pk2(p0.y, p1.y);
    unsigned long long pAz = pk2(p0.z, p1.z), pAw = pk2(p0.w, p1.w);
    unsigned long long cA  = pk2(c0, c1);
    unsigned long long pBx = pk2(p2.x, p3.x), pBy = pk2(p2.y, p3.y);
    unsigned long long pBz = pk2(p2.z, p3.z), pBw = pk2(p2.w, p3.w);
    unsigned long long cB  = pk2(c2, c3);

    unsigned long long wA = pk2(0.f, 0.f), wB = pk2(0.f, 0.f);
    for (int q = 0; q < QCH; q++) {
        float4 m = sm[q];
        float  r = srr[q];
        unsigned long long mx = pk2(m.x, m.x), my = pk2(m.y, m.y);
        unsigned long long mz = pk2(m.z, m.z), mw = pk2(m.w, m.w);
        unsigned long long rr = pk2(r, r);

        unsigned long long sA = fma2(mw, pAw, cA);
        sA = fma2(mz, pAz, sA);
        sA = fma2(my, pAy, sA);
        sA = fma2(mx, pAx, sA);
        unsigned long long sB = fma2(mw, pBw, cB);
        sB = fma2(mz, pBz, sB);
        sB = fma2(my, pBy, sB);
        sB = fma2(mx, pBx, sB);

        float s0, s1, s2, s3;
        unpk2(sA, s0, s1);
        unpk2(sB, s2, s3);
        unsigned long long eA = pk2(ex2f(s0), ex2f(s1));
        unsigned long long eB = pk2(ex2f(s2), ex2f(s3));
        wA = fma2(eA, rr, wA);
        wB = fma2(eB, rr, wB);
    }

    if (valid) {
        float w0, w1, w2, w3;
        unpk2(wA, w0, w1);
        unpk2(wB, w2, w3);
        float* dst = g_w + (size_t)b * G + kb;
        atomicAdd(dst + 0, w0);
        atomicAdd(dst + 1, w1);
        atomicAdd(dst + 2, w2);
        atomicAdd(dst + 3, w3);
    }
}

// ---------------- K3a: mean partials = w @ V (274 blocks, 16 k/thread, fewer atomics) ----------------
__global__ void __launch_bounds__(D) k3a(const float* __restrict__ V) {
    const int k0 = blockIdx.x * 16;  // 0..273, 16 k each
    const int d  = threadIdx.x;      // 128

    float v[16];
#pragma unroll
    for (int i = 0; i < 16; i++)
        v[i] = __ldg(&V[(size_t)(k0 + i) * D + d]);   // 16 independent LDGs in flight

    float acc[B];
#pragma unroll
    for (int b = 0; b < B; b++) acc[b] = 0.f;
#pragma unroll
    for (int i = 0; i < 16; i++) {
#pragma unroll
        for (int b = 0; b < B; b++)
            acc[b] = fmaf(g_w[b * G + k0 + i], v[i], acc[b]);  // uniform broadcasts
    }
#pragma unroll
    for (int b = 0; b < B; b++) atomicAdd(&g_mean[b * D + d], acc[b]);
}

// ---------------- K3b: GELU MLP head, ONE block, all batches (R12-validated) ----------------
__global__ void __launch_bounds__(512) k3b(const float* __restrict__ W1,
                                           const float* __restrict__ b1,
                                           const float* __restrict__ W2,
                                           const float* __restrict__ b2,
                                           float* __restrict__ out) {
    __shared__ float sW1[D * H1];       // 32 KB
    __shared__ float sW2[H1 * NOUT];    // 6656 B
    __shared__ float mean[B * D];       // 4 KB
    __shared__ float h[B * H1];         // 2 KB
    const int tid = threadIdx.x;        // 512

    for (int i = tid; i < D * H1 / 4; i += 512)
        ((float4*)sW1)[i] = __ldg((const float4*)W1 + i);
    for (int i = tid; i < H1 * NOUT; i += 512)
        sW2[i] = __ldg(&W2[i]);
    for (int i = tid; i < B * D; i += 512)
        mean[i] = g_mean[i] * (1.0f / (float)G);
    __syncthreads();

    {   // h: 512 outputs (b,hh), one per thread
        const int b = tid >> 6, hh = tid & 63;
        float a = b1[hh];
        const float* mrow = mean + b * D;
#pragma unroll 8
        for (int d = 0; d < D; d++)
            a = fmaf(mrow[d], sW1[d * H1 + hh], a);
        h[tid] = 0.5f * a * (1.0f + erff(a * 0.70710678118654752f));
    }
    __syncthreads();
    if (tid < B * NOUT) {   // 208 outputs (b,o)
        const int b = tid / NOUT, o = tid - b * NOUT;
        float s = b2[o];
        const float* hrow = h + b * H1;
#pragma unroll 8
        for (int j = 0; j < H1; j++)
            s = fmaf(hrow[j], sW2[j * NOUT + o], s);
        out[b * NOUT + o] = s;
    }
}

// ---------------- launch ----------------
extern "C" void kernel_launch(void* const* d_in, const int* in_sizes, int n_in,
                              void* d_out, int out_size) {
    const float* mut = (const float*)d_in[0];   // [8,4384,4]
    const float* V   = (const float*)d_in[1];   // [4384,128]
    const float* Win = (const float*)d_in[2];   // [4,128]
    const float* bin = (const float*)d_in[3];   // [128]
    const float* Kp  = (const float*)d_in[4];   // [4384,128]
    const float* W1  = (const float*)d_in[5];   // [128,64]
    const float* b1  = (const float*)d_in[6];   // [64]
    const float* W2  = (const float*)d_in[7];   // [64,26]
    const float* b2  = (const float*)d_in[8];   // [26]
    float* out = (float*)d_out;                 // [8,26]
    (void)in_sizes; (void)n_in; (void)out_size;

    k0_P<<<548, 256>>>(Win, bin, Kp);           // 4384 warps = G, + scratch zeroing
    k1_Z<<<dim3(G / 32, B), 256>>>(mut);        // (137, 8)
    k2_W<<<dim3(5, NQC, B), 256>>>(mut);        // 640 blocks
    k3a<<<274, D>>>(V);                         // 16 k per thread, 280K atomics
    k3b<<<1, 512>>>(W1, b1, W2, b2, out);
}